// round 9
// baseline (speedup 1.0000x reference)
#include <cuda_runtime.h>
#include <cuda_fp16.h>
#include <cstdint>

#define N_ROWS 16384
#define C_DIM  1024
#define NTILES 4

// ---------------- device global scratch (no allocations allowed) ----------------
__device__ float g_part[32 * 4096];       // deterministic partial column sums
__device__ float g_sig[NTILES * C_DIM];
__device__ int   g_cnt[NTILES];
__device__ int   g_work_up;               // persistent work counter (up GEMM)
__device__ int   g_rows[NTILES * N_ROWS];
__device__ __half g_xh[(size_t)N_ROWS * C_DIM];
__device__ __half g_wuh[(size_t)4096 * 1024];
__device__ __half g_wdh[(size_t)1024 * 1024];   // 4 diag blocks [e*256+n][k]
__device__ __half g_hh[(size_t)N_ROWS * 1024];  // hidden (fp16)

// ---------------- PTX helpers ----------------
static __device__ __forceinline__ uint32_t smem_u32(const void* p) {
    uint32_t a;
    asm("{ .reg .u64 t; cvta.to.shared.u64 t, %1; cvt.u32.u64 %0, t; }" : "=r"(a) : "l"(p));
    return a;
}
static __device__ __forceinline__ void cp16(uint32_t dst, const void* src, int sz) {
    asm volatile("cp.async.cg.shared.global [%0], [%1], 16, %2;" :: "r"(dst), "l"(src), "r"(sz));
}
#define CP_COMMIT() asm volatile("cp.async.commit_group;" ::: "memory")
#define CP_WAIT(n)  asm volatile("cp.async.wait_group %0;" :: "n"(n) : "memory")

static __device__ __forceinline__ void ldsm4(uint32_t* r, uint32_t addr) {
    asm volatile("ldmatrix.sync.aligned.m8n8.x4.shared.b16 {%0,%1,%2,%3}, [%4];"
                 : "=r"(r[0]), "=r"(r[1]), "=r"(r[2]), "=r"(r[3]) : "r"(addr));
}
static __device__ __forceinline__ void mma16816(float* c, const uint32_t* a, const uint32_t* b) {
    asm volatile("mma.sync.aligned.m16n8k16.row.col.f32.f16.f16.f32 "
                 "{%0,%1,%2,%3}, {%4,%5,%6,%7}, {%8,%9}, {%0,%1,%2,%3};"
                 : "+f"(c[0]), "+f"(c[1]), "+f"(c[2]), "+f"(c[3])
                 : "r"(a[0]), "r"(a[1]), "r"(a[2]), "r"(a[3]), "r"(b[0]), "r"(b[1]));
}

// 128B-row swizzle (Swizzle<3,4,3>): 16B-group g' = g ^ (row & 7)
static __device__ __forceinline__ uint32_t swz(int row, int g) {
    return (uint32_t)row * 128 + (uint32_t)((g ^ (row & 7)) << 4);
}

// ---------------------------------------------------------------------------
// Phase 1: partial column sums of w_up (32-row chunks) FUSED with fp16 convert.
__global__ void sig_sum_kernel(const float* __restrict__ w_up) {
    int bx = blockIdx.x;
    int t  = bx >> 8, cb = (bx >> 5) & 7, rc = bx & 31;
    int c  = cb * 128 + threadIdx.x;
    int row0 = t * 1024 + rc * 32;
    const float* base = w_up + (size_t)row0 * C_DIM + c;
    float s = 0.f;
    #pragma unroll 8
    for (int r = 0; r < 32; r++) {
        float v = base[(size_t)r * C_DIM];
        s += v;
        g_wuh[(size_t)(row0 + r) * C_DIM + c] = __float2half_rn(v);
    }
    g_part[rc * 4096 + t * C_DIM + c] = s;
}

// Phase 2: fixed-order combine + sign; resets routing + work counters.
__global__ void sign_kernel() {
    int i = blockIdx.x * 256 + threadIdx.x;
    if (blockIdx.x == 0 && threadIdx.x < NTILES) g_cnt[threadIdx.x] = 0;
    if (blockIdx.x == 0 && threadIdx.x == NTILES) g_work_up = 0;
    float s = 0.f;
    #pragma unroll
    for (int rc = 0; rc < 32; rc++) s += g_part[rc * 4096 + i];
    g_sig[i] = (s > 0.f) ? 1.f : ((s < 0.f) ? -1.f : 0.f);
}

// routing (fp32, exact argmax semantics) + fp16 convert of x, vectorized.
__global__ void route_kernel(const float* __restrict__ x,
                             float* __restrict__ gate_out, int write_gate) {
    __shared__ float red[NTILES][128];
    int n = blockIdx.x;
    int tid = threadIdx.x;
    const float4* xr = reinterpret_cast<const float4*>(x + (size_t)n * C_DIM);
    float a[NTILES] = {0.f, 0.f, 0.f, 0.f};
    __half hh[8];
    #pragma unroll
    for (int q = 0; q < 2; q++) {
        int k4 = tid * 2 + q;              // float4 index 0..255
        float4 v = xr[k4];
        #pragma unroll
        for (int t = 0; t < NTILES; t++) {
            const float4 sg = reinterpret_cast<const float4*>(g_sig + t * C_DIM)[k4];
            a[t] += v.x * sg.x + v.y * sg.y + v.z * sg.z + v.w * sg.w;
        }
        hh[q * 4 + 0] = __float2half_rn(v.x);
        hh[q * 4 + 1] = __float2half_rn(v.y);
        hh[q * 4 + 2] = __float2half_rn(v.z);
        hh[q * 4 + 3] = __float2half_rn(v.w);
    }
    *reinterpret_cast<uint4*>(g_xh + (size_t)n * C_DIM + tid * 8) = *reinterpret_cast<uint4*>(hh);

    #pragma unroll
    for (int t = 0; t < NTILES; t++) red[t][tid] = a[t];
    __syncthreads();
    for (int s = 64; s > 0; s >>= 1) {
        if (tid < s) {
            #pragma unroll
            for (int t = 0; t < NTILES; t++) red[t][tid] += red[t][tid + s];
        }
        __syncthreads();
    }
    if (tid == 0) {
        float best = red[0][0];
        int w = 0;
        #pragma unroll
        for (int t = 1; t < NTILES; t++)
            if (red[t][0] > best) { best = red[t][0]; w = t; }
        int pos = atomicAdd(&g_cnt[w], 1);
        g_rows[w * N_ROWS + pos] = n;
        if (write_gate) {
            #pragma unroll
            for (int t = 0; t < NTILES; t++)
                gate_out[(size_t)n * NTILES + t] = (t == w) ? 1.f : 0.f;
        }
    }
}

// w_down diag blocks -> fp16, float4 vectorized: 256K float4
__global__ void split_wdown_kernel(const float* __restrict__ w) {
    size_t i = (size_t)blockIdx.x * 256 + threadIdx.x;   // float4 index
    size_t el = i * 4;
    int e = (int)(el >> 18);
    int n = (int)((el >> 10) & 255);
    int k = (int)(el & 1023);
    float4 v = *reinterpret_cast<const float4*>(w + (size_t)(e * 256 + n) * 4096 + e * 1024 + k);
    __half2 a = __halves2half2(__float2half_rn(v.x), __float2half_rn(v.y));
    __half2 b = __halves2half2(__float2half_rn(v.z), __float2half_rn(v.w));
    reinterpret_cast<__half2*>(g_wdh)[i * 2]     = a;
    reinterpret_cast<__half2*>(g_wdh)[i * 2 + 1] = b;
}

// ---------------------------------------------------------------------------
// UP GEMM, PERSISTENT: plain fp16 (A = xh, B = wuh), fp32 accum.
// 296 persistent CTAs (2/SM) steal (expert, m-tile, n-tile) items from
// g_work_up. Tile: 128 gathered rows x 128 cols, 256 threads.
// K = 1024 in 16 chunks of 64. Stage 32KB: A(16K) | B(16K), Swizzle<3,4,3>.
// 3-stage pipeline (96KB dynamic). Epilogue: bias+ReLU -> g_hh (fp16).
// ---------------------------------------------------------------------------
__global__ void __launch_bounds__(256, 2)
gemm_up_kernel(const float* __restrict__ bias)
{
    const int tid = threadIdx.x;

    extern __shared__ __align__(1024) uint8_t dynraw[];
    __shared__ int rs[128];
    __shared__ float bsh[128];
    __shared__ int wsh;
    const uint32_t dynu = smem_u32(dynraw);

    // per-expert tile counts + prefix (counts are final: route ran before us)
    int te[NTILES], pre[NTILES + 1];
    pre[0] = 0;
    #pragma unroll
    for (int t = 0; t < NTILES; t++) {
        te[t] = ((g_cnt[t] + 127) >> 7) << 3;    // ceil(cnt/128) * 8 n-tiles
        pre[t + 1] = pre[t] + te[t];
    }
    const int total = pre[NTILES];

    const int lane = tid & 31, w = tid >> 5;
    const int wm = w >> 1, wn = w & 1;
    const int gid = lane >> 2, qid = lane & 3;

    uint32_t aoff[2][4], boff[4][4];
    #pragma unroll
    for (int mi = 0; mi < 2; mi++)
        #pragma unroll
        for (int s16 = 0; s16 < 4; s16++) {
            int row = wm * 32 + mi * 16 + (lane & 15);
            aoff[mi][s16] = swz(row, s16 * 2 + (lane >> 4));
        }
    #pragma unroll
    for (int nb = 0; nb < 4; nb++)
        #pragma unroll
        for (int s16 = 0; s16 < 4; s16++) {
            int rown = wn * 64 + nb * 16 + (lane & 7) + ((lane >> 4) << 3);
            boff[nb][s16] = swz(rown, s16 * 2 + ((lane >> 3) & 1));
        }

    while (true) {
        if (tid == 0) wsh = atomicAdd(&g_work_up, 1);
        __syncthreads();
        const int item = wsh;
        if (item >= total) break;

        int e = 0;
        #pragma unroll
        for (int t = 1; t < NTILES; t++) if (item >= pre[t]) e = t;
        const int local = item - pre[e];
        const int m0 = (local >> 3) << 7;
        const int n0 = (local & 7) << 7;
        const int cnt = g_cnt[e];
        const int brow0 = e * 1024 + n0;

        if (tid < 128) {
            int m = m0 + tid;
            rs[tid]  = (m < cnt) ? g_rows[e * N_ROWS + m] : -1;
            bsh[tid] = bias[brow0 + tid];
        }
        __syncthreads();

        auto load_stage = [&](int ch, int slot) {
            const uint32_t sb = dynu + slot * 32768;
            #pragma unroll
            for (int l = 0; l < 4; l++) {        // A: 128 rows x 8 groups
                int i = tid * 4 + l;
                int row = i >> 3, g = i & 7;
                uint32_t off = swz(row, g);
                int r = rs[row];
                const size_t ak = (size_t)(r < 0 ? 0 : r) * 1024 + ch * 64 + g * 8;
                cp16(sb + off, g_xh + ak, (r < 0) ? 0 : 16);
            }
            #pragma unroll
            for (int l = 0; l < 4; l++) {        // B: 128 rows x 8 groups
                int j = tid * 4 + l;
                int row = j >> 3, g = j & 7;
                uint32_t off = swz(row, g);
                const size_t bk = (size_t)(brow0 + row) * 1024 + ch * 64 + g * 8;
                cp16(sb + 16384 + off, g_wuh + bk, 16);
            }
        };

        float acc[2][8][4];
        #pragma unroll
        for (int mi = 0; mi < 2; mi++)
            #pragma unroll
            for (int nj = 0; nj < 8; nj++)
                #pragma unroll
                for (int q = 0; q < 4; q++) acc[mi][nj][q] = 0.f;

        load_stage(0, 0); CP_COMMIT();
        load_stage(1, 1); CP_COMMIT();

        for (int ch = 0; ch < 16; ch++) {
            CP_WAIT(1);
            __syncthreads();
            const uint32_t sb = dynu + (ch % 3) * 32768;

            #pragma unroll
            for (int s16 = 0; s16 < 4; s16++) {
                uint32_t ah[2][4];
                #pragma unroll
                for (int mi = 0; mi < 2; mi++)
                    ldsm4(ah[mi], sb + aoff[mi][s16]);
                uint32_t bh[4][4];
                #pragma unroll
                for (int nb = 0; nb < 4; nb++)
                    ldsm4(bh[nb], sb + 16384 + boff[nb][s16]);
                #pragma unroll
                for (int mi = 0; mi < 2; mi++)
                    #pragma unroll
                    for (int nj = 0; nj < 8; nj++)
                        mma16816(acc[mi][nj], ah[mi], &bh[nj >> 1][(nj & 1) * 2]);
            }

            if (ch + 2 < 16) load_stage(ch + 2, (ch + 2) % 3);
            CP_COMMIT();
        }
        CP_WAIT(0);
        __syncthreads();

        // epilogue: bias + ReLU -> fp16, SMEM stage, coalesced stores
        uint32_t* stg = reinterpret_cast<uint32_t*>(dynraw);   // pitch 68 u32
        #pragma unroll
        for (int mi = 0; mi < 2; mi++)
            #pragma unroll
            for (int nj = 0; nj < 8; nj++) {
                int col0 = wn * 64 + nj * 8 + 2 * qid;
                int r0 = wm * 32 + mi * 16 + gid;
                float b0 = bsh[col0], b1 = bsh[col0 + 1];
                float v0 = fmaxf(acc[mi][nj][0] + b0, 0.f);
                float v1 = fmaxf(acc[mi][nj][1] + b1, 0.f);
                float v2 = fmaxf(acc[mi][nj][2] + b0, 0.f);
                float v3 = fmaxf(acc[mi][nj][3] + b1, 0.f);
                __half2 p01 = __halves2half2(__float2half_rn(v0), __float2half_rn(v1));
                __half2 p23 = __halves2half2(__float2half_rn(v2), __float2half_rn(v3));
                int cp = col0 >> 1;
                stg[r0 * 68 + cp]       = *reinterpret_cast<uint32_t*>(&p01);
                stg[(r0 + 8) * 68 + cp] = *reinterpret_cast<uint32_t*>(&p23);
            }
        __syncthreads();
        uint32_t* dst32 = reinterpret_cast<uint32_t*>(g_hh);
        for (int i = tid; i < 2048; i += 256) {
            int row = i >> 4, q = i & 15;
            int r = rs[row];
            if (r < 0) continue;
            uint4 v = *reinterpret_cast<uint4*>(&stg[row * 68 + q * 4]);
            *reinterpret_cast<uint4*>(&dst32[(size_t)r * 512 + (n0 >> 1) + q * 4]) = v;
        }
        __syncthreads();   // protect rs/bsh/stg before next item
    }
}

// ---------------------------------------------------------------------------
// DOWN GEMM: 1-term fp16 (A = hh, B = wdh), fp32 accum.
// CTA: 128 gathered rows x 256 cols, 512 threads, K = 1024 in 16 chunks of 64.
// Stage 48KB: A(16K) | B(32K); 3-stage. Epilogue: bias -> out slice + zeros.
// ---------------------------------------------------------------------------
__global__ void __launch_bounds__(512, 1)
gemm_down_kernel(const float* __restrict__ bias, float* __restrict__ outp)
{
    const int e   = blockIdx.z;
    const int cnt = g_cnt[e];
    const int m0  = blockIdx.y * 128;
    if (m0 >= cnt) return;
    const int tid = threadIdx.x;

    extern __shared__ __align__(1024) uint8_t dynraw[];
    __shared__ int rs[128];
    __shared__ float bsh[256];
    const uint32_t dynu = smem_u32(dynraw);

    const int brow0 = e * 256;

    if (tid < 128) {
        int m = m0 + tid;
        rs[tid] = (m < cnt) ? g_rows[e * N_ROWS + m] : -1;
    }
    if (tid < 256) bsh[tid] = bias[brow0 + tid];
    __syncthreads();

    auto load_stage = [&](int ch, int slot) {
        const uint32_t sb = dynu + slot * 49152;
        #pragma unroll
        for (int l = 0; l < 2; l++) {        // A: 128 rows x 8 groups
            int i = tid * 2 + l;
            int row = i >> 3, g = i & 7;
            uint32_t off = swz(row, g);
            int r = rs[row];
            const size_t ak = (size_t)(r < 0 ? 0 : r) * 1024 + ch * 64 + g * 8;
            cp16(sb + off, g_hh + ak, (r < 0) ? 0 : 16);
        }
        #pragma unroll
        for (int l = 0; l < 4; l++) {        // B: 256 rows x 8 groups
            int j = tid * 4 + l;
            int row = j >> 3, g = j & 7;
            uint32_t off = swz(row, g);
            const size_t bk = (size_t)(brow0 + row) * 1024 + ch * 64 + g * 8;
            cp16(sb + 16384 + off, g_wdh + bk, 16);
        }
    };

    const int lane = tid & 31, w = tid >> 5;
    const int wm = w >> 2, wn = w & 3;
    const int gid = lane >> 2, qid = lane & 3;

    uint32_t aoff[2][4], boff[4][4];
    #pragma unroll
    for (int mi = 0; mi < 2; mi++)
        #pragma unroll
        for (int s16 = 0; s16 < 4; s16++) {
            int row = wm * 32 + mi * 16 + (lane & 15);
            aoff[mi][s16] = swz(row, s16 * 2 + (lane >> 4));
        }
    #pragma unroll
    for (int nb = 0; nb < 4; nb++)
        #pragma unroll
        for (int s16 = 0; s16 < 4; s16++) {
            int rown = wn * 64 + nb * 16 + (lane & 7) + ((lane >> 4) << 3);
            boff[nb][s16] = swz(rown, s16 * 2 + ((lane >> 3) & 1));
        }

    float acc[2][8][4];
    #pragma unroll
    for (int mi = 0; mi < 2; mi++)
        #pragma unroll
        for (int nj = 0; nj < 8; nj++)
            #pragma unroll
            for (int q = 0; q < 4; q++) acc[mi][nj][q] = 0.f;

    load_stage(0, 0); CP_COMMIT();
    load_stage(1, 1); CP_COMMIT();

    for (int ch = 0; ch < 16; ch++) {
        CP_WAIT(1);
        __syncthreads();
        const uint32_t sb = dynu + (ch % 3) * 49152;

        #pragma unroll
        for (int s16 = 0; s16 < 4; s16++) {
            uint32_t ah[2][4];
            #pragma unroll
            for (int mi = 0; mi < 2; mi++)
                ldsm4(ah[mi], sb + aoff[mi][s16]);
            uint32_t bh[4][4];
            #pragma unroll
            for (int nb = 0; nb < 4; nb++)
                ldsm4(bh[nb], sb + 16384 + boff[nb][s16]);
            #pragma unroll
            for (int mi = 0; mi < 2; mi++)
                #pragma unroll
                for (int nj = 0; nj < 8; nj++)
                    mma16816(acc[mi][nj], ah[mi], &bh[nj >> 1][(nj & 1) * 2]);
        }

        if (ch + 2 < 16) load_stage(ch + 2, (ch + 2) % 3);
        CP_COMMIT();
    }
    CP_WAIT(0);
    __syncthreads();

    // epilogue: two 128-col fp32 passes + zero-fill other 768 cols
    float* stgf = reinterpret_cast<float*>(dynraw);
    #pragma unroll
    for (int pass = 0; pass < 2; pass++) {
        if ((wn >> 1) == pass) {
            #pragma unroll
            for (int mi = 0; mi < 2; mi++)
                #pragma unroll
                for (int nj = 0; nj < 8; nj++) {
                    int col0 = wn * 64 + nj * 8 + 2 * qid;
                    int r0 = wm * 32 + mi * 16 + gid;
                    float b0 = bsh[col0], b1 = bsh[col0 + 1];
                    int cl = col0 - pass * 128;
                    stgf[r0 * 132 + cl]           = acc[mi][nj][0] + b0;
                    stgf[r0 * 132 + cl + 1]       = acc[mi][nj][1] + b1;
                    stgf[(r0 + 8) * 132 + cl]     = acc[mi][nj][2] + b0;
                    stgf[(r0 + 8) * 132 + cl + 1] = acc[mi][nj][3] + b1;
                }
        }
        __syncthreads();
        for (int i = tid; i < 4096; i += 512) {
            int row = i >> 5, q = i & 31;
            int r = rs[row];
            if (r < 0) continue;
            float4 v = *reinterpret_cast<float4*>(&stgf[row * 132 + q * 4]);
            *reinterpret_cast<float4*>(&outp[(size_t)r * C_DIM + e * 256 + pass * 128 + q * 4]) = v;
        }
        __syncthreads();
    }
    const float4 z4 = make_float4(0.f, 0.f, 0.f, 0.f);
    for (int i = tid; i < 128 * 192; i += 512) {
        int row = i / 192, j = i - row * 192;
        int r = rs[row];
        if (r < 0) continue;
        int zcol = j * 4;
        if (zcol >= e * 256) zcol += 256;
        *reinterpret_cast<float4*>(&outp[(size_t)r * C_DIM + zcol]) = z4;
    }
}

// ---------------------------------------------------------------------------
extern "C" void kernel_launch(void* const* d_in, const int* in_sizes, int n_in,
                              void* d_out, int out_size) {
    const float* x      = (const float*)d_in[0];
    const float* w_up   = (const float*)d_in[1];
    const float* b_up   = (const float*)d_in[2];
    const float* w_down = (const float*)d_in[3];
    const float* b_down = (const float*)d_in[4];
    float* out = (float*)d_out;

    const size_t out_elems = (size_t)N_ROWS * C_DIM;
    int write_gate = (out_size >= (int)(out_elems + (size_t)N_ROWS * NTILES)) ? 1 : 0;

    static int attr_done = 0;
    if (!attr_done) {
        cudaFuncSetAttribute(gemm_up_kernel,   cudaFuncAttributeMaxDynamicSharedMemorySize, 98304);
        cudaFuncSetAttribute(gemm_down_kernel, cudaFuncAttributeMaxDynamicSharedMemorySize, 147456);
        attr_done = 1;
    }

    sig_sum_kernel<<<1024, 128>>>(w_up);                               // 0
    sign_kernel<<<16, 256>>>();                                        // 1
    route_kernel<<<N_ROWS, 128>>>(x, out + out_elems, write_gate);     // 2
    gemm_up_kernel<<<296, 256, 98304>>>(b_up);                         // 3 (profiled)
    split_wdown_kernel<<<1024, 256>>>(w_down);                         // 4
    gemm_down_kernel<<<dim3(1, 128, NTILES), 512, 147456>>>(b_down, out); // 5
}